// round 1
// baseline (speedup 1.0000x reference)
#include <cuda_runtime.h>

#define TT       64
#define NN       2048
#define RPB      16                 // rows of w owned per CTA
#define NCTA     (NN / RPB)         // 128 CTAs
#define NTHREADS 512
#define NWARPS   (NTHREADS / 32)    // 16
#define CPW      (NN / NWARPS)      // 128 columns per warp

// shared-memory layout (floats)
#define SM_W     0
#define SM_TP    (RPB * NN)                 // 32768
#define SM_TPO   (SM_TP + NN)
#define SM_Z     (SM_TPO + NN)
#define SM_V     (SM_Z + NN)
#define SM_X     (SM_V + RPB)
#define SM_PART  (SM_X + RPB)
#define SM_TOTAL (SM_PART + RPB * NWARPS)
#define SMEM_BYTES (SM_TOTAL * sizeof(float))

// ---- global sense-reversing barrier (all CTAs co-resident: 1 CTA/SM) ----
__device__ unsigned g_bar_count = 0;
__device__ unsigned g_bar_gen   = 0;

__device__ __forceinline__ void grid_barrier() {
    __syncthreads();
    if (threadIdx.x == 0) {
        __threadfence();
        unsigned gen = *((volatile unsigned*)&g_bar_gen);
        if (atomicAdd(&g_bar_count, 1u) == NCTA - 1u) {
            g_bar_count = 0;           // reset for next use
            __threadfence();
            atomicAdd(&g_bar_gen, 1u); // release
        } else {
            while (*((volatile unsigned*)&g_bar_gen) == gen) __nanosleep(64);
        }
        __threadfence();
    }
    __syncthreads();
}

// clip helper: jnp.clip(x, 0, 1)
__device__ __forceinline__ float clip01(float x) {
    return fminf(fmaxf(x, 0.0f), 1.0f);
}

__global__ void __launch_bounds__(NTHREADS, 1)
snn_persistent(const float* __restrict__ exc,
               const float* __restrict__ w_in,
               const float* __restrict__ tpre_in,
               const float* __restrict__ tpost_in,
               float* __restrict__ out)
{
    extern __shared__ float sm[];
    float* w_s   = sm + SM_W;     // RPB x NN, row-major
    float* tp_s  = sm + SM_TP;    // NN (pre-trace, full population)
    float* tpo_s = sm + SM_TPO;   // NN (post-trace, full population)
    float* z_s   = sm + SM_Z;     // NN (previous-step spikes)
    float* v_s   = sm + SM_V;     // RPB (own membrane potentials)
    float* x_s   = sm + SM_X;     // RPB (own input current this step)
    float* part  = sm + SM_PART;  // RPB x NWARPS partial i_syn

    const int tid     = threadIdx.x;
    const int warp    = tid >> 5;
    const int lane    = tid & 31;
    const int rowBase = blockIdx.x * RPB;

    // ---- prologue: load own 16 rows of w into smem (only DRAM traffic) ----
    {
        const float4* src = reinterpret_cast<const float4*>(w_in + (size_t)rowBase * NN);
        float4*       dst = reinterpret_cast<float4*>(w_s);
        #pragma unroll 8
        for (int i = tid; i < RPB * NN / 4; i += NTHREADS) dst[i] = src[i];
    }
    for (int i = tid; i < NN; i += NTHREADS) {
        tp_s[i]  = tpre_in[i];
        tpo_s[i] = tpost_in[i];
        z_s[i]   = 0.0f;
    }
    if (tid < RPB) v_s[tid] = 0.0f;
    __syncthreads();

    const int colBase = warp * CPW + lane * 4;   // this lane's 4 columns

    for (int t = 0; t < TT; ++t) {
        // prefetch this step's input current for own neurons
        if (tid < RPB) x_s[tid] = exc[t * NN + rowBase + tid];

        // ---- fused pass: apply dw_{t-1} to w, compute i_syn = w_new @ z_{t-1} ----
        // Each warp owns a 128-column block; tp/z for those columns loaded once
        // per 16 rows (amortized). Smem traffic ~8B/element (w RMW).
        if (t > 0) {
            const float4 zv = *reinterpret_cast<const float4*>(&z_s[colBase]);
            const float4 pv = *reinterpret_cast<const float4*>(&tp_s[colBase]);
            #pragma unroll
            for (int r = 0; r < RPB; ++r) {
                // dw[i,j] = 1e-3*(z[i]*tp[j]) - 1e-3*(tpo[i]*z[j]);  z in {0,1}
                // a = 1e-3*z[i] (exact: 0 or 1e-3f), b = 1e-3*tpo[i]
                const float a = __fmul_rn(1e-3f, z_s[rowBase + r]);
                const float b = __fmul_rn(1e-3f, tpo_s[rowBase + r]);
                float4 wv = *reinterpret_cast<float4*>(&w_s[r * NN + colBase]);

                wv.x = clip01(__fadd_rn(wv.x, __fsub_rn(__fmul_rn(a, pv.x), __fmul_rn(b, zv.x))));
                wv.y = clip01(__fadd_rn(wv.y, __fsub_rn(__fmul_rn(a, pv.y), __fmul_rn(b, zv.y))));
                wv.z = clip01(__fadd_rn(wv.z, __fsub_rn(__fmul_rn(a, pv.z), __fmul_rn(b, zv.z))));
                wv.w = clip01(__fadd_rn(wv.w, __fsub_rn(__fmul_rn(a, pv.w), __fmul_rn(b, zv.w))));

                *reinterpret_cast<float4*>(&w_s[r * NN + colBase]) = wv;

                float acc = wv.x * zv.x;
                acc = fmaf(wv.y, zv.y, acc);
                acc = fmaf(wv.z, zv.z, acc);
                acc = fmaf(wv.w, zv.w, acc);
                #pragma unroll
                for (int off = 16; off; off >>= 1)
                    acc += __shfl_xor_sync(0xffffffffu, acc, off);
                if (lane == 0) part[r * NWARPS + warp] = acc;
            }
        }
        __syncthreads();

        // ---- neuron update for own 16 rows ----
        if (tid < RPB) {
            float isyn = 0.0f;
            if (t > 0) {
                #pragma unroll
                for (int k = 0; k < NWARPS; ++k) isyn += part[tid * NWARPS + k];
            }
            float v = v_s[tid];
            // v = v + 0.1*((0 - v) + i_syn + x)
            v = __fadd_rn(v, __fmul_rn(0.1f,
                    __fadd_rn(__fadd_rn(__fsub_rn(0.0f, v), isyn), x_s[tid])));
            const float zn = (__fsub_rn(v, 1.0f) > 0.0f) ? 1.0f : 0.0f;
            v_s[tid] = (zn > 0.0f) ? 0.0f : v;   // reset
            out[t * NN + rowBase + tid] = zn;    // publish spike (also the output)
        }

        grid_barrier();   // z_t visible to all CTAs

        // ---- read full z_t from out row t; update traces (replicated locally) ----
        {
            const int i0 = tid * 4;   // 512 threads * 4 = 2048
            const float4 zr = *reinterpret_cast<const float4*>(&out[(size_t)t * NN + i0]);
            *reinterpret_cast<float4*>(&z_s[i0]) = zr;

            float4 p = *reinterpret_cast<float4*>(&tp_s[i0]);
            float4 q = *reinterpret_cast<float4*>(&tpo_s[i0]);
            // tp  = tp  + 0.05*(-tp  + z)
            p.x = __fadd_rn(p.x, __fmul_rn(0.05f, __fadd_rn(-p.x, zr.x)));
            p.y = __fadd_rn(p.y, __fmul_rn(0.05f, __fadd_rn(-p.y, zr.y)));
            p.z = __fadd_rn(p.z, __fmul_rn(0.05f, __fadd_rn(-p.z, zr.z)));
            p.w = __fadd_rn(p.w, __fmul_rn(0.05f, __fadd_rn(-p.w, zr.w)));
            // tpo = tpo + 0.05*(-tpo + z)
            q.x = __fadd_rn(q.x, __fmul_rn(0.05f, __fadd_rn(-q.x, zr.x)));
            q.y = __fadd_rn(q.y, __fmul_rn(0.05f, __fadd_rn(-q.y, zr.y)));
            q.z = __fadd_rn(q.z, __fmul_rn(0.05f, __fadd_rn(-q.z, zr.z)));
            q.w = __fadd_rn(q.w, __fmul_rn(0.05f, __fadd_rn(-q.w, zr.w)));
            *reinterpret_cast<float4*>(&tp_s[i0])  = p;
            *reinterpret_cast<float4*>(&tpo_s[i0]) = q;
        }
        __syncthreads();   // traces/z ready for next step's fused pass
    }
}

extern "C" void kernel_launch(void* const* d_in, const int* in_sizes, int n_in,
                              void* d_out, int out_size) {
    const float* exc   = (const float*)d_in[0];  // [T, N]
    const float* w     = (const float*)d_in[1];  // [N, N]
    const float* tpre  = (const float*)d_in[2];  // [N]
    const float* tpost = (const float*)d_in[3];  // [N]
    float*       out   = (float*)d_out;          // [T, N]

    cudaFuncSetAttribute(snn_persistent,
                         cudaFuncAttributeMaxDynamicSharedMemorySize,
                         (int)SMEM_BYTES);
    snn_persistent<<<NCTA, NTHREADS, SMEM_BYTES>>>(exc, w, tpre, tpost, out);
}